// round 15
// baseline (speedup 1.0000x reference)
#include <cuda_runtime.h>

// ConvEnhanced: 2x2 valid conv + ReLU -> channel 0.
//
// Quantum circuit collapses analytically:
//   RZ layers = diagonal phases (|amp|^2 invariant), CNOTs = permutations,
//   Z0 after two 'full' CNOT layers == Z0*Z1*Z3 on the RX product state
//   => qval = cos(p00)*cos(p01)*cos(p11); qparams provably irrelevant.
// Channel 1 = qval replicated over each 2x2 patch.
//
// x: [64,1,257,257] f32; out: [64,2,256,256] f32.
//
// R15 (= R13/R14 resubmitted after two broker-side infra failures):
// R12 best config (1 thread/patch, 1M threads, 256-thr blocks, __cosf,
// float2 stores) + warp-shuffle tap sharing: lane i's col-(c+2) tap equals
// lane i+1's col-c tap, so each row needs only 2 LDGs + 1 SHFL (lane 31
// loads its own edge tap). Warp load wavefronts 18 -> ~13.
// Warps never cross the pw wrap (128 % 32 == 0), so the shuffle is exact.

#define IN_HW   257
#define OUT_HW  256
#define HP      128
#define BATCH   64
#define N_PATCH (BATCH * HP * HP)   // 1,048,576

__global__ __launch_bounds__(256)
void conv_enhanced_kernel(const float* __restrict__ x,
                          const float* __restrict__ w,
                          const float* __restrict__ bias,
                          float* __restrict__ out)
{
    const int idx = blockIdx.x * blockDim.x + threadIdx.x;   // exact grid
    const int pw = idx & (HP - 1);
    const int ph = (idx >> 7) & (HP - 1);
    const int b  = idx >> 14;
    const unsigned lane = threadIdx.x & 31;

    const float w00 = __ldg(w + 0);
    const float w01 = __ldg(w + 1);
    const float w10 = __ldg(w + 2);
    const float w11 = __ldg(w + 3);
    const float bb  = __ldg(bias);

    const int r = ph * 2;
    const int c = pw * 2;
    const float* row0 = x + (size_t)b * (IN_HW * IN_HW) + r * IN_HW + c;
    const float* row1 = row0 + IN_HW;
    const float* row2 = row1 + IN_HW;

    // two taps per row loaded; third tap shared from lane+1 via shuffle
    const float x00 = __ldg(row0 + 0), x01 = __ldg(row0 + 1);
    const float x10 = __ldg(row1 + 0), x11 = __ldg(row1 + 1);
    const float x20 = __ldg(row2 + 0), x21 = __ldg(row2 + 1);

    float x02 = __shfl_down_sync(0xffffffffu, x00, 1);
    float x12 = __shfl_down_sync(0xffffffffu, x10, 1);
    float x22 = __shfl_down_sync(0xffffffffu, x20, 1);
    if (lane == 31) {                 // edge lane loads its own third tap
        x02 = __ldg(row0 + 2);
        x12 = __ldg(row1 + 2);
        x22 = __ldg(row2 + 2);
    }

    const float p00 = fmaxf(fmaf(w00, x00, fmaf(w01, x01, fmaf(w10, x10, fmaf(w11, x11, bb)))), 0.f);
    const float p01 = fmaxf(fmaf(w00, x01, fmaf(w01, x02, fmaf(w10, x11, fmaf(w11, x12, bb)))), 0.f);
    const float p10 = fmaxf(fmaf(w00, x10, fmaf(w01, x11, fmaf(w10, x20, fmaf(w11, x21, bb)))), 0.f);
    const float p11 = fmaxf(fmaf(w00, x11, fmaf(w01, x12, fmaf(w10, x21, fmaf(w11, x22, bb)))), 0.f);

    const float q = __cosf(p00) * __cosf(p01) * __cosf(p11);

    float* ob = out + (size_t)b * (2 * OUT_HW * OUT_HW);
    const int o0 = r * OUT_HW + c;                 // c even -> 8B aligned

    // channel 0: conv + relu
    *reinterpret_cast<float2*>(ob + o0)          = make_float2(p00, p01);
    *reinterpret_cast<float2*>(ob + o0 + OUT_HW) = make_float2(p10, p11);
    // channel 1: qmap replicated 2x2
    float* ob1 = ob + OUT_HW * OUT_HW;
    const float2 qq = make_float2(q, q);
    *reinterpret_cast<float2*>(ob1 + o0)          = qq;
    *reinterpret_cast<float2*>(ob1 + o0 + OUT_HW) = qq;
}

extern "C" void kernel_launch(void* const* d_in, const int* in_sizes, int n_in,
                              void* d_out, int out_size)
{
    const float* x      = (const float*)d_in[0];
    const float* conv_w = (const float*)d_in[1];
    const float* conv_b = (const float*)d_in[2];
    // d_in[3] = qparams: provably unused
    float* out = (float*)d_out;

    const int threads = 256;
    const int blocks  = N_PATCH / threads;   // 4096
    conv_enhanced_kernel<<<blocks, threads>>>(x, conv_w, conv_b, out);
}

// round 17
// speedup vs baseline: 1.3821x; 1.3821x over previous
#include <cuda_runtime.h>

// ConvEnhanced: 2x2 valid conv + ReLU -> channel 0.
//
// Quantum circuit collapses analytically:
//   RZ layers = diagonal phases (|amp|^2 invariant), CNOTs = permutations,
//   Z0 after two 'full' CNOT layers == Z0*Z1*Z3 on the RX product state
//   => qval = cos(p00)*cos(p01)*cos(p11); qparams provably irrelevant.
// Channel 1 = qval replicated over each 2x2 patch.
//
// x: [64,1,257,257] f32; out: [64,2,256,256] f32.
//
// R16 = R12 best config (1 thread/patch, 1M threads, 256-thr blocks,
// __cosf, float2 stores) + parity-uniform float2 LOADS:
//   row base parity P=(b+r)&1 is warp-uniform, so per row an 8B-aligned
//   float2 covers two of the three taps (at c or c+1 depending on parity)
//   plus one scalar. 9 LDG -> 6 LDG, load wavefronts 18 -> ~12, with NO
//   inter-lane coupling (the R15 shuffle regression's failure mode).

#define IN_HW   257
#define OUT_HW  256
#define HP      128
#define BATCH   64
#define N_PATCH (BATCH * HP * HP)   // 1,048,576

__device__ __forceinline__ float2 ld2(const float* p)
{
    return *reinterpret_cast<const float2*>(p);   // 8B-aligned by construction
}

__global__ __launch_bounds__(256)
void conv_enhanced_kernel(const float* __restrict__ x,
                          const float* __restrict__ w,
                          const float* __restrict__ bias,
                          float* __restrict__ out)
{
    const int idx = blockIdx.x * blockDim.x + threadIdx.x;   // exact grid
    const int pw = idx & (HP - 1);
    const int ph = (idx >> 7) & (HP - 1);
    const int b  = idx >> 14;

    const float w00 = __ldg(w + 0);
    const float w01 = __ldg(w + 1);
    const float w10 = __ldg(w + 2);
    const float w11 = __ldg(w + 3);
    const float bb  = __ldg(bias);

    const int r = ph * 2;
    const int c = pw * 2;
    const float* row0 = x + (size_t)b * (IN_HW * IN_HW) + r * IN_HW + c;
    const float* row1 = row0 + IN_HW;
    const float* row2 = row1 + IN_HW;

    // Row-base element parity: (b*66049 + r*257 + c) & 1 == (b + r) & 1
    // (c even, 66049 & 257 odd). Warp-uniform -> non-divergent branch.
    float x00, x01, x02, x10, x11, x12, x20, x21, x22;
    if (((b + r) & 1) == 0) {
        // rows 0,2 aligned at c; row 1 aligned at c+1
        const float2 a0 = ld2(row0);     x00 = a0.x; x01 = a0.y; x02 = __ldg(row0 + 2);
        x10 = __ldg(row1);               const float2 a1 = ld2(row1 + 1); x11 = a1.x; x12 = a1.y;
        const float2 a2 = ld2(row2);     x20 = a2.x; x21 = a2.y; x22 = __ldg(row2 + 2);
    } else {
        // rows 0,2 aligned at c+1; row 1 aligned at c
        x00 = __ldg(row0);               const float2 a0 = ld2(row0 + 1); x01 = a0.x; x02 = a0.y;
        const float2 a1 = ld2(row1);     x10 = a1.x; x11 = a1.y; x12 = __ldg(row1 + 2);
        x20 = __ldg(row2);               const float2 a2 = ld2(row2 + 1); x21 = a2.x; x22 = a2.y;
    }

    const float p00 = fmaxf(fmaf(w00, x00, fmaf(w01, x01, fmaf(w10, x10, fmaf(w11, x11, bb)))), 0.f);
    const float p01 = fmaxf(fmaf(w00, x01, fmaf(w01, x02, fmaf(w10, x11, fmaf(w11, x12, bb)))), 0.f);
    const float p10 = fmaxf(fmaf(w00, x10, fmaf(w01, x11, fmaf(w10, x20, fmaf(w11, x21, bb)))), 0.f);
    const float p11 = fmaxf(fmaf(w00, x11, fmaf(w01, x12, fmaf(w10, x21, fmaf(w11, x22, bb)))), 0.f);

    const float q = __cosf(p00) * __cosf(p01) * __cosf(p11);

    float* ob = out + (size_t)b * (2 * OUT_HW * OUT_HW);
    const int o0 = r * OUT_HW + c;                 // c even -> 8B aligned

    // channel 0: conv + relu
    *reinterpret_cast<float2*>(ob + o0)          = make_float2(p00, p01);
    *reinterpret_cast<float2*>(ob + o0 + OUT_HW) = make_float2(p10, p11);
    // channel 1: qmap replicated 2x2
    float* ob1 = ob + OUT_HW * OUT_HW;
    const float2 qq = make_float2(q, q);
    *reinterpret_cast<float2*>(ob1 + o0)          = qq;
    *reinterpret_cast<float2*>(ob1 + o0 + OUT_HW) = qq;
}

extern "C" void kernel_launch(void* const* d_in, const int* in_sizes, int n_in,
                              void* d_out, int out_size)
{
    const float* x      = (const float*)d_in[0];
    const float* conv_w = (const float*)d_in[1];
    const float* conv_b = (const float*)d_in[2];
    // d_in[3] = qparams: provably unused
    float* out = (float*)d_out;

    const int threads = 256;
    const int blocks  = N_PATCH / threads;   // 4096
    conv_enhanced_kernel<<<blocks, threads>>>(x, conv_w, conv_b, out);
}